// round 3
// baseline (speedup 1.0000x reference)
#include <cuda_runtime.h>

#define EPSV 1e-5f

// ---------------- scratch (device globals; no allocation allowed) ----------------
__device__ float g_p1[8ull * 128 * 128 * 128];   // pooled stage 1: (B,C,128,128)
__device__ float g_p2[8ull * 128 * 64 * 64];     // pooled stage 2: (B,C,64,64)
__device__ float g_part[8ull * 32 * 128 * 128];  // gram partials: (B, 32 splits, C, C)
__device__ float g_S[8ull * 128 * 128];          // sim[b][k][c] (softmaxed)

// ---------------- kernel 1/2: depthwise 3x3 s2 p1 + BN + PReLU ----------------
__global__ void dwconv_bn_prelu_kernel(
    const float* __restrict__ in, float* __restrict__ out,
    const float* __restrict__ w,
    const float* __restrict__ gamma, const float* __restrict__ beta,
    const float* __restrict__ mean, const float* __restrict__ var,
    const float* __restrict__ alpha,
    int Hin, int Win, int Hout, int Wout)
{
    int bc = blockIdx.z;           // b*128 + c
    int c  = bc & 127;
    int ox = blockIdx.x * 32 + threadIdx.x;
    int oy = blockIdx.y * 8 + threadIdx.y;

    const float* ip = in + (size_t)bc * Hin * Win;
    float w0 = w[c*9+0], w1 = w[c*9+1], w2 = w[c*9+2];
    float w3 = w[c*9+3], w4 = w[c*9+4], w5 = w[c*9+5];
    float w6 = w[c*9+6], w7 = w[c*9+7], w8 = w[c*9+8];
    float inv  = gamma[c] * rsqrtf(var[c] + EPSV);
    float bias = beta[c] - mean[c] * inv;
    float a    = alpha[c];

    int iy = 2 * oy - 1;
    int ix = 2 * ox - 1;
    bool top  = (iy >= 0);
    bool left = (ix >= 0);

    const float* r0 = ip + (size_t)iy * Win + ix;
    const float* r1 = r0 + Win;
    const float* r2 = r1 + Win;

    float s = 0.f;
    if (top) {
        if (left) s += w0 * r0[0];
        s += w1 * r0[1];
        s += w2 * r0[2];
    }
    if (left) s += w3 * r1[0];
    s += w4 * r1[1];
    s += w5 * r1[2];
    if (left) s += w6 * r2[0];
    s += w7 * r2[1];
    s += w8 * r2[2];

    float y = s * inv + bias;
    out[(size_t)bc * Hout * Wout + (size_t)oy * Wout + ox] = (y > 0.f) ? y : a * y;
}

// ---------------- kernel 3: gram partials  G_s[b,i,j] = sum_{n in chunk s} p2[b,i,n] p2[b,j,n] ----
// grid: (32 n-chunks, 8 batches), 256 threads, 64 KB dynamic smem, smem layout P[n][c]
__global__ __launch_bounds__(256) void gram_partial_kernel()
{
    extern __shared__ float P[];       // [128 n][128 c]
    int s = blockIdx.x, b = blockIdx.y;
    int tid = threadIdx.x;

    const float* src = g_p2 + (size_t)b * 128 * 4096 + (size_t)s * 128;
    // load transposed: thread (c, ngroup) reads float4 along n, scatters into P[n][c]
    for (int idx = tid; idx < 4096; idx += 256) {
        int c = idx & 127, ng = idx >> 7;
        float4 v = *(const float4*)(src + (size_t)c * 4096 + ng * 4);
        P[(ng * 4 + 0) * 128 + c] = v.x;
        P[(ng * 4 + 1) * 128 + c] = v.y;
        P[(ng * 4 + 2) * 128 + c] = v.z;
        P[(ng * 4 + 3) * 128 + c] = v.w;
    }
    __syncthreads();

    int i0 = (tid >> 4) * 8;
    int j0 = (tid & 15) * 8;
    float acc[8][8];
#pragma unroll
    for (int ii = 0; ii < 8; ++ii)
#pragma unroll
        for (int jj = 0; jj < 8; ++jj) acc[ii][jj] = 0.f;

    for (int n = 0; n < 128; ++n) {
        const float* row = P + n * 128;
        float4 a0 = *(const float4*)(row + i0);
        float4 a1 = *(const float4*)(row + i0 + 4);
        float4 b0 = *(const float4*)(row + j0);
        float4 b1 = *(const float4*)(row + j0 + 4);
        float ai[8] = {a0.x, a0.y, a0.z, a0.w, a1.x, a1.y, a1.z, a1.w};
        float bj[8] = {b0.x, b0.y, b0.z, b0.w, b1.x, b1.y, b1.z, b1.w};
#pragma unroll
        for (int ii = 0; ii < 8; ++ii)
#pragma unroll
            for (int jj = 0; jj < 8; ++jj)
                acc[ii][jj] = fmaf(ai[ii], bj[jj], acc[ii][jj]);
    }

    float* dst = g_part + ((size_t)b * 32 + s) * 16384;
#pragma unroll
    for (int ii = 0; ii < 8; ++ii) {
        float4 v0 = make_float4(acc[ii][0], acc[ii][1], acc[ii][2], acc[ii][3]);
        float4 v1 = make_float4(acc[ii][4], acc[ii][5], acc[ii][6], acc[ii][7]);
        float* op = dst + (size_t)(i0 + ii) * 128 + j0;
        *(float4*)op = v0;
        *(float4*)(op + 4) = v1;
    }
}

// ---------------- kernel 4: reduce partials, scale, softmax over j; store sim[b][i][j] ----------
// grid (128 rows i, 8 batches), 128 threads (j)
__global__ void softmax_kernel()
{
    int i = blockIdx.x, b = blockIdx.y, j = threadIdx.x;
    const float* p = g_part + (size_t)b * 32 * 16384 + (size_t)i * 128 + j;
    float g = 0.f;
#pragma unroll
    for (int s = 0; s < 32; ++s) g += p[(size_t)s * 16384];
    g *= (1.0f / 64.0f);   // (64*64)^-0.5

    __shared__ float buf[128];
    buf[j] = g;
    __syncthreads();
    for (int off = 64; off > 0; off >>= 1) {
        if (j < off) buf[j] = fmaxf(buf[j], buf[j + off]);
        __syncthreads();
    }
    float m = buf[0];
    __syncthreads();
    float e = __expf(g - m);
    buf[j] = e;
    __syncthreads();
    for (int off = 64; off > 0; off >>= 1) {
        if (j < off) buf[j] = buf[j] + buf[j + off];
        __syncthreads();
    }
    float r = e / buf[0];
    g_S[(size_t)b * 16384 + (size_t)i * 128 + j] = r;
}

// ---------------- kernel 5: out[b,c,n] = sum_k sim[b,k,c] * x[b,k,n] ----------------
// grid (256 tile-groups, 8 batches), 256 threads, 128 KB dyn smem. 2 n-tiles of 128 per block.
#define FMA2(d, a, b, c) asm("fma.rn.f32x2 %0, %1, %2, %3;" : "=l"(d) : "l"(a), "l"(b), "l"(c))

__global__ __launch_bounds__(256) void attn_out_kernel(const float* __restrict__ x,
                                                       float* __restrict__ out)
{
    extern __shared__ float sm[];
    float* Ws = sm;            // [k][c]  = sim[b][k][c], 128x128
    float* Xs = sm + 16384;    // [k][n]  tile, 128x128

    int b = blockIdx.y;
    int tid = threadIdx.x;

    const float* Sp = g_S + (size_t)b * 16384;
    for (int idx = tid; idx < 4096; idx += 256)
        *(float4*)(Ws + idx * 4) = *(const float4*)(Sp + idx * 4);

    const float* xb = x + (size_t)b * 128 * 65536;
    float*       ob = out + (size_t)b * 128 * 65536;

    int c0 = (tid >> 4) * 8;
    int nn = (tid & 15) * 8;

    for (int t = 0; t < 2; ++t) {
        int n0 = (blockIdx.x * 2 + t) * 128;
        __syncthreads();   // Ws ready / previous Xs fully consumed
        for (int idx = tid; idx < 4096; idx += 256) {
            int k = idx >> 5, c4 = idx & 31;
            *(float4*)(Xs + k * 128 + c4 * 4) =
                *(const float4*)(xb + (size_t)k * 65536 + n0 + c4 * 4);
        }
        __syncthreads();

        unsigned long long acc[8][4];
#pragma unroll
        for (int cc = 0; cc < 8; ++cc)
#pragma unroll
            for (int q = 0; q < 4; ++q) acc[cc][q] = 0ull;

#pragma unroll 4
        for (int k = 0; k < 128; ++k) {
            const float* wr = Ws + k * 128 + c0;
            const float* xr = Xs + k * 128 + nn;
            ulonglong2 xA = *(const ulonglong2*)xr;        // n pairs (0,1),(2,3)
            ulonglong2 xB = *(const ulonglong2*)(xr + 4);  // n pairs (4,5),(6,7)
            unsigned long long xp0 = xA.x, xp1 = xA.y, xp2 = xB.x, xp3 = xB.y;
            float4 wlo = *(const float4*)wr;
            float4 whi = *(const float4*)(wr + 4);
            float wv[8] = {wlo.x, wlo.y, wlo.z, wlo.w, whi.x, whi.y, whi.z, whi.w};
#pragma unroll
            for (int cc = 0; cc < 8; ++cc) {
                unsigned long long wp;
                unsigned wu = __float_as_uint(wv[cc]);
                asm("mov.b64 %0, {%1, %1};" : "=l"(wp) : "r"(wu));  // splat {w,w}
                FMA2(acc[cc][0], wp, xp0, acc[cc][0]);
                FMA2(acc[cc][1], wp, xp1, acc[cc][1]);
                FMA2(acc[cc][2], wp, xp2, acc[cc][2]);
                FMA2(acc[cc][3], wp, xp3, acc[cc][3]);
            }
        }

#pragma unroll
        for (int cc = 0; cc < 8; ++cc) {
            float* op = ob + (size_t)(c0 + cc) * 65536 + n0 + nn;
            ulonglong2 v0; v0.x = acc[cc][0]; v0.y = acc[cc][1];
            ulonglong2 v1; v1.x = acc[cc][2]; v1.y = acc[cc][3];
            *(ulonglong2*)op = v0;
            *(ulonglong2*)(op + 4) = v1;
        }
    }
}

// ---------------- launch ----------------
extern "C" void kernel_launch(void* const* d_in, const int* in_sizes, int n_in,
                              void* d_out, int out_size)
{
    (void)in_sizes; (void)n_in; (void)out_size;
    const float* x    = (const float*)d_in[0];
    const float* c1w  = (const float*)d_in[1];
    const float* g1   = (const float*)d_in[2];
    const float* b1   = (const float*)d_in[3];
    const float* m1   = (const float*)d_in[4];
    const float* v1   = (const float*)d_in[5];
    const float* a1   = (const float*)d_in[6];
    const float* c2w  = (const float*)d_in[7];
    const float* g2   = (const float*)d_in[8];
    const float* b2   = (const float*)d_in[9];
    const float* m2   = (const float*)d_in[10];
    const float* v2   = (const float*)d_in[11];
    const float* a2   = (const float*)d_in[12];
    float* out = (float*)d_out;

    void* tmp;
    cudaGetSymbolAddress(&tmp, g_p1);  float* p1 = (float*)tmp;
    cudaGetSymbolAddress(&tmp, g_p2);  float* p2 = (float*)tmp;

    cudaFuncSetAttribute(gram_partial_kernel,
                         cudaFuncAttributeMaxDynamicSharedMemorySize, 65536);
    cudaFuncSetAttribute(attn_out_kernel,
                         cudaFuncAttributeMaxDynamicSharedMemorySize, 131072);

    dim3 blk(32, 8);
    dwconv_bn_prelu_kernel<<<dim3(4, 16, 1024), blk>>>(x, p1, c1w, g1, b1, m1, v1, a1,
                                                       256, 256, 128, 128);
    dwconv_bn_prelu_kernel<<<dim3(2, 8, 1024), blk>>>(p1, p2, c2w, g2, b2, m2, v2, a2,
                                                      128, 128, 64, 64);
    gram_partial_kernel<<<dim3(32, 8), 256, 65536>>>();
    softmax_kernel<<<dim3(128, 8), 128>>>();
    attn_out_kernel<<<dim3(256, 8), 256, 131072>>>(x, out);
}

// round 4
// speedup vs baseline: 1.9826x; 1.9826x over previous
#include <cuda_runtime.h>
#include <cuda_bf16.h>

#define EPSV 1e-5f

// ---------------- scratch (device globals; no allocation allowed) ----------------
__device__ float g_p1[8ull * 128 * 128 * 128];   // pooled stage 1: (B,C,128,128)
__device__ float g_p2[8ull * 128 * 64 * 64];     // pooled stage 2: (B,C,64,64)
__device__ float g_part[8ull * 32 * 128 * 128];  // gram partials: (B, 32 splits, C, C)
__device__ float g_St[8ull * 128 * 128];         // sim transposed: [b][c][k]

// ---------------- kernel 1/2: depthwise 3x3 s2 p1 + BN + PReLU ----------------
__global__ void dwconv_bn_prelu_kernel(
    const float* __restrict__ in, float* __restrict__ out,
    const float* __restrict__ w,
    const float* __restrict__ gamma, const float* __restrict__ beta,
    const float* __restrict__ mean, const float* __restrict__ var,
    const float* __restrict__ alpha,
    int Hin, int Win, int Hout, int Wout)
{
    int bc = blockIdx.z;           // b*128 + c
    int c  = bc & 127;
    int ox = blockIdx.x * 32 + threadIdx.x;
    int oy = blockIdx.y * 8 + threadIdx.y;

    const float* ip = in + (size_t)bc * Hin * Win;
    float w0 = w[c*9+0], w1 = w[c*9+1], w2 = w[c*9+2];
    float w3 = w[c*9+3], w4 = w[c*9+4], w5 = w[c*9+5];
    float w6 = w[c*9+6], w7 = w[c*9+7], w8 = w[c*9+8];
    float inv  = gamma[c] * rsqrtf(var[c] + EPSV);
    float bias = beta[c] - mean[c] * inv;
    float a    = alpha[c];

    int iy = 2 * oy - 1;
    int ix = 2 * ox - 1;
    bool top  = (iy >= 0);
    bool left = (ix >= 0);

    const float* r0 = ip + (size_t)iy * Win + ix;
    const float* r1 = r0 + Win;
    const float* r2 = r1 + Win;

    float s = 0.f;
    if (top) {
        if (left) s += w0 * r0[0];
        s += w1 * r0[1];
        s += w2 * r0[2];
    }
    if (left) s += w3 * r1[0];
    s += w4 * r1[1];
    s += w5 * r1[2];
    if (left) s += w6 * r2[0];
    s += w7 * r2[1];
    s += w8 * r2[2];

    float y = s * inv + bias;
    out[(size_t)bc * Hout * Wout + (size_t)oy * Wout + ox] = (y > 0.f) ? y : a * y;
}

// ---------------- kernel 3: gram partials ----------------
__global__ __launch_bounds__(256) void gram_partial_kernel()
{
    extern __shared__ float P[];       // [128 n][128 c]
    int s = blockIdx.x, b = blockIdx.y;
    int tid = threadIdx.x;

    const float* src = g_p2 + (size_t)b * 128 * 4096 + (size_t)s * 128;
    for (int idx = tid; idx < 4096; idx += 256) {
        int c = idx & 127, ng = idx >> 7;
        float4 v = *(const float4*)(src + (size_t)c * 4096 + ng * 4);
        P[(ng * 4 + 0) * 128 + c] = v.x;
        P[(ng * 4 + 1) * 128 + c] = v.y;
        P[(ng * 4 + 2) * 128 + c] = v.z;
        P[(ng * 4 + 3) * 128 + c] = v.w;
    }
    __syncthreads();

    int i0 = (tid >> 4) * 8;
    int j0 = (tid & 15) * 8;
    float acc[8][8];
#pragma unroll
    for (int ii = 0; ii < 8; ++ii)
#pragma unroll
        for (int jj = 0; jj < 8; ++jj) acc[ii][jj] = 0.f;

    for (int n = 0; n < 128; ++n) {
        const float* row = P + n * 128;
        float4 a0 = *(const float4*)(row + i0);
        float4 a1 = *(const float4*)(row + i0 + 4);
        float4 b0 = *(const float4*)(row + j0);
        float4 b1 = *(const float4*)(row + j0 + 4);
        float ai[8] = {a0.x, a0.y, a0.z, a0.w, a1.x, a1.y, a1.z, a1.w};
        float bj[8] = {b0.x, b0.y, b0.z, b0.w, b1.x, b1.y, b1.z, b1.w};
#pragma unroll
        for (int ii = 0; ii < 8; ++ii)
#pragma unroll
            for (int jj = 0; jj < 8; ++jj)
                acc[ii][jj] = fmaf(ai[ii], bj[jj], acc[ii][jj]);
    }

    float* dst = g_part + ((size_t)b * 32 + s) * 16384;
#pragma unroll
    for (int ii = 0; ii < 8; ++ii) {
        float4 v0 = make_float4(acc[ii][0], acc[ii][1], acc[ii][2], acc[ii][3]);
        float4 v1 = make_float4(acc[ii][4], acc[ii][5], acc[ii][6], acc[ii][7]);
        float* op = dst + (size_t)(i0 + ii) * 128 + j0;
        *(float4*)op = v0;
        *(float4*)(op + 4) = v1;
    }
}

// ---------------- kernel 4: reduce partials, scale, softmax; store TRANSPOSED sim ----
// g_St[b][c][k] = softmax_over_c( G[b][k][:] )[c]
__global__ void softmax_kernel()
{
    int i = blockIdx.x, b = blockIdx.y, j = threadIdx.x;   // i = row k, j = col c
    const float* p = g_part + (size_t)b * 32 * 16384 + (size_t)i * 128 + j;
    float g = 0.f;
#pragma unroll
    for (int s = 0; s < 32; ++s) g += p[(size_t)s * 16384];
    g *= (1.0f / 64.0f);   // (64*64)^-0.5

    __shared__ float buf[128];
    buf[j] = g;
    __syncthreads();
    for (int off = 64; off > 0; off >>= 1) {
        if (j < off) buf[j] = fmaxf(buf[j], buf[j + off]);
        __syncthreads();
    }
    float m = buf[0];
    __syncthreads();
    float e = __expf(g - m);
    buf[j] = e;
    __syncthreads();
    for (int off = 64; off > 0; off >>= 1) {
        if (j < off) buf[j] = buf[j] + buf[j + off];
        __syncthreads();
    }
    float r = e / buf[0];
    // transposed store: row = c (j), col = k (i)
    g_St[(size_t)b * 16384 + (size_t)j * 128 + i] = r;
}

// ---------------- kernel 5: out[b,c,n] = sum_k sim[b,k,c] * x[b,k,n] via bf16-split MMA ----
#define LDA 136
#define LDB 136
#define NT  4   // n-tiles (128 wide) per block

__device__ __forceinline__ unsigned smem_u32(const void* p) {
    return (unsigned)__cvta_generic_to_shared(p);
}

#define LDSM_X4(r, addr) \
    asm volatile("ldmatrix.sync.aligned.m8n8.x4.shared.b16 {%0,%1,%2,%3},[%4];" \
        : "=r"((r)[0]), "=r"((r)[1]), "=r"((r)[2]), "=r"((r)[3]) : "r"(addr))

#define LDSM_X4_T(r, addr) \
    asm volatile("ldmatrix.sync.aligned.m8n8.x4.trans.shared.b16 {%0,%1,%2,%3},[%4];" \
        : "=r"((r)[0]), "=r"((r)[1]), "=r"((r)[2]), "=r"((r)[3]) : "r"(addr))

#define MMA16816(C, A, b0, b1) \
    asm volatile("mma.sync.aligned.m16n8k16.row.col.f32.bf16.bf16.f32 " \
        "{%0,%1,%2,%3},{%4,%5,%6,%7},{%8,%9},{%0,%1,%2,%3};" \
        : "+f"((C)[0]), "+f"((C)[1]), "+f"((C)[2]), "+f"((C)[3]) \
        : "r"((A)[0]), "r"((A)[1]), "r"((A)[2]), "r"((A)[3]), "r"(b0), "r"(b1))

#define CP_ASYNC16(dst, src) \
    asm volatile("cp.async.cg.shared.global [%0],[%1],16;" :: "r"(dst), "l"(src))
#define CP_COMMIT() asm volatile("cp.async.commit_group;")
#define CP_WAIT0()  asm volatile("cp.async.wait_group 0;")

__device__ __forceinline__ void split2(float a, float b,
                                       __nv_bfloat162& hi, __nv_bfloat162& lo)
{
    __nv_bfloat16 ha = __float2bfloat16(a);
    __nv_bfloat16 hb = __float2bfloat16(b);
    hi = __halves2bfloat162(ha, hb);
    lo = __halves2bfloat162(__float2bfloat16(a - __bfloat162float(ha)),
                            __float2bfloat16(b - __bfloat162float(hb)));
}

__global__ __launch_bounds__(256) void attn_mma_kernel(const float* __restrict__ x,
                                                       float* __restrict__ out)
{
    extern __shared__ char smraw[];
    __nv_bfloat16* Ahi = (__nv_bfloat16*)smraw;        // [128 c][LDA k]
    __nv_bfloat16* Alo = Ahi + 128 * LDA;
    __nv_bfloat16* Bhi = Alo + 128 * LDA;              // [128 k][LDB n]
    __nv_bfloat16* Blo = Bhi + 128 * LDB;
    float* Xs = (float*)(Blo + 128 * LDB);             // staging [128 k][128 n] fp32

    int b    = blockIdx.y;
    int tid  = threadIdx.x;
    int warp = tid >> 5, lane = tid & 31;

    const float* xb = x + (size_t)b * 128 * 65536;
    float*       ob = out + (size_t)b * 128 * 65536;

    // ---- prefetch tile 0 via cp.async
    {
        int n0 = blockIdx.x * NT * 128;
#pragma unroll
        for (int i = 0; i < 16; ++i) {
            int idx = i * 256 + tid;
            int k = idx >> 5, c4 = idx & 31;
            CP_ASYNC16(smem_u32(Xs + k * 128 + c4 * 4),
                       xb + (size_t)k * 65536 + n0 + c4 * 4);
        }
        CP_COMMIT();
    }

    // ---- A prep: g_St[b] ([c][k] fp32) -> bf16 hi/lo
    {
        const float* Sp = g_St + (size_t)b * 16384;
#pragma unroll
        for (int i = 0; i < 16; ++i) {
            int idx = i * 256 + tid;
            int c = idx >> 5, k4 = idx & 31;
            float4 v = *(const float4*)(Sp + c * 128 + k4 * 4);
            __nv_bfloat162 h0, l0, h1, l1;
            split2(v.x, v.y, h0, l0);
            split2(v.z, v.w, h1, l1);
            __nv_bfloat16* ph = Ahi + c * LDA + k4 * 4;
            __nv_bfloat16* pl = Alo + c * LDA + k4 * 4;
            *(__nv_bfloat162*)(ph)     = h0;
            *(__nv_bfloat162*)(ph + 2) = h1;
            *(__nv_bfloat162*)(pl)     = l0;
            *(__nv_bfloat162*)(pl + 2) = l1;
        }
    }

    // ---- convert tile 0: Xs -> Bhi/Blo (each thread converts its own staged elems)
    CP_WAIT0();
#pragma unroll
    for (int i = 0; i < 16; ++i) {
        int idx = i * 256 + tid;
        int k = idx >> 5, c4 = idx & 31;
        float4 v = *(const float4*)(Xs + k * 128 + c4 * 4);
        __nv_bfloat162 h0, l0, h1, l1;
        split2(v.x, v.y, h0, l0);
        split2(v.z, v.w, h1, l1);
        __nv_bfloat16* ph = Bhi + k * LDB + c4 * 4;
        __nv_bfloat16* pl = Blo + k * LDB + c4 * 4;
        *(__nv_bfloat162*)(ph)     = h0;
        *(__nv_bfloat162*)(ph + 2) = h1;
        *(__nv_bfloat162*)(pl)     = l0;
        *(__nv_bfloat162*)(pl + 2) = l1;
    }
    __syncthreads();

    int mw = (warp >> 1) * 32;        // warp c-offset (4 warps over 128)
    int nw = (warp & 1) * 64;         // warp n-offset (2 warps over 128)
    int r  = lane & 15, q = lane >> 4;

    for (int t = 0; t < NT; ++t) {
        int n0 = (blockIdx.x * NT + t) * 128;

        // prefetch next tile into staging while we compute
        if (t + 1 < NT) {
            int n0n = n0 + 128;
#pragma unroll
            for (int i = 0; i < 16; ++i) {
                int idx = i * 256 + tid;
                int k = idx >> 5, c4 = idx & 31;
                CP_ASYNC16(smem_u32(Xs + k * 128 + c4 * 4),
                           xb + (size_t)k * 65536 + n0n + c4 * 4);
            }
            CP_COMMIT();
        }

        float acc[2][8][4];
#pragma unroll
        for (int mf = 0; mf < 2; ++mf)
#pragma unroll
            for (int nf = 0; nf < 8; ++nf)
#pragma unroll
                for (int e = 0; e < 4; ++e) acc[mf][nf][e] = 0.f;

#pragma unroll
        for (int ks = 0; ks < 8; ++ks) {
            int k0 = ks * 16;
            unsigned ah[2][4], al[2][4];
#pragma unroll
            for (int mf = 0; mf < 2; ++mf) {
                unsigned aaddr = smem_u32(Ahi + (mw + mf * 16 + r) * LDA + k0 + q * 8);
                LDSM_X4(ah[mf], aaddr);
                unsigned laddr = smem_u32(Alo + (mw + mf * 16 + r) * LDA + k0 + q * 8);
                LDSM_X4(al[mf], laddr);
            }
#pragma unroll
            for (int nc = 0; nc < 4; ++nc) {
                unsigned bh[4], bl[4];
                unsigned bhaddr = smem_u32(Bhi + (k0 + r) * LDB + nw + nc * 16 + q * 8);
                LDSM_X4_T(bh, bhaddr);
                unsigned bladdr = smem_u32(Blo + (k0 + r) * LDB + nw + nc * 16 + q * 8);
                LDSM_X4_T(bl, bladdr);
#pragma unroll
                for (int mf = 0; mf < 2; ++mf) {
#pragma unroll
                    for (int h = 0; h < 2; ++h) {
                        float* C = acc[mf][nc * 2 + h];
                        MMA16816(C, ah[mf], bh[2 * h], bh[2 * h + 1]);  // hi*hi
                        MMA16816(C, ah[mf], bl[2 * h], bl[2 * h + 1]);  // hi*lo
                        MMA16816(C, al[mf], bh[2 * h], bh[2 * h + 1]);  // lo*hi
                    }
                }
            }
        }

        __syncthreads();   // everyone done reading Bhi/Blo

        // convert prefetched tile into Bhi/Blo (per-thread private mapping w.r.t. Xs)
        if (t + 1 < NT) {
            CP_WAIT0();
#pragma unroll
            for (int i = 0; i < 16; ++i) {
                int idx = i * 256 + tid;
                int k = idx >> 5, c4 = idx & 31;
                float4 v = *(const float4*)(Xs + k * 128 + c4 * 4);
                __nv_bfloat162 h0, l0, h1, l1;
                split2(v.x, v.y, h0, l0);
                split2(v.z, v.w, h1, l1);
                __nv_bfloat16* ph = Bhi + k * LDB + c4 * 4;
                __nv_bfloat16* pl = Blo + k * LDB + c4 * 4;
                *(__nv_bfloat162*)(ph)     = h0;
                *(__nv_bfloat162*)(ph + 2) = h1;
                *(__nv_bfloat162*)(pl)     = l0;
                *(__nv_bfloat162*)(pl + 2) = l1;
            }
        }

        // epilogue: store acc to gmem (overlaps with other warps' converts)
        int rbase = mw + (lane >> 2);
        int cbase = nw + ((lane & 3) << 1);
#pragma unroll
        for (int mf = 0; mf < 2; ++mf) {
#pragma unroll
            for (int nf = 0; nf < 8; ++nf) {
                float* p0 = ob + (size_t)(rbase + mf * 16) * 65536 + n0 + cbase + nf * 8;
                float* p1 = p0 + 8ull * 65536;
                *(float2*)p0 = make_float2(acc[mf][nf][0], acc[mf][nf][1]);
                *(float2*)p1 = make_float2(acc[mf][nf][2], acc[mf][nf][3]);
            }
        }

        __syncthreads();   // B refill visible to all before next mma round
    }
}

// ---------------- launch ----------------
extern "C" void kernel_launch(void* const* d_in, const int* in_sizes, int n_in,
                              void* d_out, int out_size)
{
    (void)in_sizes; (void)n_in; (void)out_size;
    const float* x    = (const float*)d_in[0];
    const float* c1w  = (const float*)d_in[1];
    const float* g1   = (const float*)d_in[2];
    const float* b1   = (const float*)d_in[3];
    const float* m1   = (const float*)d_in[4];
    const float* v1   = (const float*)d_in[5];
    const float* a1   = (const float*)d_in[6];
    const float* c2w  = (const float*)d_in[7];
    const float* g2   = (const float*)d_in[8];
    const float* b2   = (const float*)d_in[9];
    const float* m2   = (const float*)d_in[10];
    const float* v2   = (const float*)d_in[11];
    const float* a2   = (const float*)d_in[12];
    float* out = (float*)d_out;

    void* tmp;
    cudaGetSymbolAddress(&tmp, g_p1);  float* p1 = (float*)tmp;
    cudaGetSymbolAddress(&tmp, g_p2);  float* p2 = (float*)tmp;

    // smem: A(hi+lo) 2*128*136*2 + B(hi+lo) 2*128*136*2 + stage 128*128*4 = 204800
    cudaFuncSetAttribute(gram_partial_kernel,
                         cudaFuncAttributeMaxDynamicSharedMemorySize, 65536);
    cudaFuncSetAttribute(attn_mma_kernel,
                         cudaFuncAttributeMaxDynamicSharedMemorySize, 204800);

    dim3 blk(32, 8);
    dwconv_bn_prelu_kernel<<<dim3(4, 16, 1024), blk>>>(x, p1, c1w, g1, b1, m1, v1, a1,
                                                       256, 256, 128, 128);
    dwconv_bn_prelu_kernel<<<dim3(2, 8, 1024), blk>>>(p1, p2, c2w, g2, b2, m2, v2, a2,
                                                      128, 128, 64, 64);
    gram_partial_kernel<<<dim3(32, 8), 256, 65536>>>();
    softmax_kernel<<<dim3(128, 8), 128>>>();
    attn_mma_kernel<<<dim3(128, 8), 256, 204800>>>(x, out);
}

// round 6
// speedup vs baseline: 2.3059x; 1.1631x over previous
#include <cuda_runtime.h>
#include <cuda_fp16.h>
#include <cstdint>

#define EPSV 1e-5f

// ---------------- scratch (device globals; no allocation allowed) ----------------
__device__ float g_p1[8ull * 128 * 128 * 128];   // pooled stage 1: (B,C,128,128)
__device__ float g_p2[8ull * 128 * 64 * 64];     // pooled stage 2: (B,C,64,64)
__device__ float g_part[8ull * 32 * 128 * 128];  // gram partials: (B, 32 splits, C, C)
__device__ float g_St[8ull * 128 * 128];         // sim transposed: [b][c][k]

// ---------------- kernel 1/2: depthwise 3x3 s2 p1 + BN + PReLU ----------------
__global__ void dwconv_bn_prelu_kernel(
    const float* __restrict__ in, float* __restrict__ out,
    const float* __restrict__ w,
    const float* __restrict__ gamma, const float* __restrict__ beta,
    const float* __restrict__ mean, const float* __restrict__ var,
    const float* __restrict__ alpha,
    int Hin, int Win, int Hout, int Wout)
{
    int bc = blockIdx.z;           // b*128 + c
    int c  = bc & 127;
    int ox = blockIdx.x * 32 + threadIdx.x;
    int oy = blockIdx.y * 8 + threadIdx.y;

    const float* ip = in + (size_t)bc * Hin * Win;
    float w0 = w[c*9+0], w1 = w[c*9+1], w2 = w[c*9+2];
    float w3 = w[c*9+3], w4 = w[c*9+4], w5 = w[c*9+5];
    float w6 = w[c*9+6], w7 = w[c*9+7], w8 = w[c*9+8];
    float inv  = gamma[c] * rsqrtf(var[c] + EPSV);
    float bias = beta[c] - mean[c] * inv;
    float a    = alpha[c];

    int iy = 2 * oy - 1;
    int ix = 2 * ox - 1;
    bool top  = (iy >= 0);
    bool left = (ix >= 0);

    const float* r0 = ip + (size_t)iy * Win + ix;
    const float* r1 = r0 + Win;
    const float* r2 = r1 + Win;

    float s = 0.f;
    if (top) {
        if (left) s += w0 * r0[0];
        s += w1 * r0[1];
        s += w2 * r0[2];
    }
    if (left) s += w3 * r1[0];
    s += w4 * r1[1];
    s += w5 * r1[2];
    if (left) s += w6 * r2[0];
    s += w7 * r2[1];
    s += w8 * r2[2];

    float y = s * inv + bias;
    out[(size_t)bc * Hout * Wout + (size_t)oy * Wout + ox] = (y > 0.f) ? y : a * y;
}

// ---------------- kernel 3: gram partials ----------------
__global__ __launch_bounds__(256) void gram_partial_kernel()
{
    extern __shared__ float P[];       // [128 n][128 c]
    int s = blockIdx.x, b = blockIdx.y;
    int tid = threadIdx.x;

    const float* src = g_p2 + (size_t)b * 128 * 4096 + (size_t)s * 128;
    for (int idx = tid; idx < 4096; idx += 256) {
        int c = idx & 127, ng = idx >> 7;
        float4 v = *(const float4*)(src + (size_t)c * 4096 + ng * 4);
        P[(ng * 4 + 0) * 128 + c] = v.x;
        P[(ng * 4 + 1) * 128 + c] = v.y;
        P[(ng * 4 + 2) * 128 + c] = v.z;
        P[(ng * 4 + 3) * 128 + c] = v.w;
    }
    __syncthreads();

    int i0 = (tid >> 4) * 8;
    int j0 = (tid & 15) * 8;
    float acc[8][8];
#pragma unroll
    for (int ii = 0; ii < 8; ++ii)
#pragma unroll
        for (int jj = 0; jj < 8; ++jj) acc[ii][jj] = 0.f;

    for (int n = 0; n < 128; ++n) {
        const float* row = P + n * 128;
        float4 a0 = *(const float4*)(row + i0);
        float4 a1 = *(const float4*)(row + i0 + 4);
        float4 b0 = *(const float4*)(row + j0);
        float4 b1 = *(const float4*)(row + j0 + 4);
        float ai[8] = {a0.x, a0.y, a0.z, a0.w, a1.x, a1.y, a1.z, a1.w};
        float bj[8] = {b0.x, b0.y, b0.z, b0.w, b1.x, b1.y, b1.z, b1.w};
#pragma unroll
        for (int ii = 0; ii < 8; ++ii)
#pragma unroll
            for (int jj = 0; jj < 8; ++jj)
                acc[ii][jj] = fmaf(ai[ii], bj[jj], acc[ii][jj]);
    }

    float* dst = g_part + ((size_t)b * 32 + s) * 16384;
#pragma unroll
    for (int ii = 0; ii < 8; ++ii) {
        float4 v0 = make_float4(acc[ii][0], acc[ii][1], acc[ii][2], acc[ii][3]);
        float4 v1 = make_float4(acc[ii][4], acc[ii][5], acc[ii][6], acc[ii][7]);
        float* op = dst + (size_t)(i0 + ii) * 128 + j0;
        *(float4*)op = v0;
        *(float4*)(op + 4) = v1;
    }
}

// ---------------- kernel 4: reduce, scale, softmax; store TRANSPOSED sim ----
__global__ void softmax_kernel()
{
    int i = blockIdx.x, b = blockIdx.y, j = threadIdx.x;   // i = row k, j = col c
    const float* p = g_part + (size_t)b * 32 * 16384 + (size_t)i * 128 + j;
    float g = 0.f;
#pragma unroll
    for (int s = 0; s < 32; ++s) g += p[(size_t)s * 16384];
    g *= (1.0f / 64.0f);   // (64*64)^-0.5

    __shared__ float buf[128];
    buf[j] = g;
    __syncthreads();
    for (int off = 64; off > 0; off >>= 1) {
        if (j < off) buf[j] = fmaxf(buf[j], buf[j + off]);
        __syncthreads();
    }
    float m = buf[0];
    __syncthreads();
    float e = __expf(g - m);
    buf[j] = e;
    __syncthreads();
    for (int off = 64; off > 0; off >>= 1) {
        if (j < off) buf[j] = buf[j] + buf[j + off];
        __syncthreads();
    }
    float r = e / buf[0];
    g_St[(size_t)b * 16384 + (size_t)j * 128 + i] = r;   // [b][c][k]
}

// ---------------- kernel 5: out[b,c,n] = sum_k sim[b,k,c]*x[b,k,n], fp16 2-product MMA ----
// A = sim (split hi/lo fp16, ~22-bit mantissa), B = x (single fp16).
#define LDA 136
#define LDB 136
#define NT  4   // n-tiles (128 wide) per block

__device__ __forceinline__ unsigned smem_u32(const void* p) {
    return (unsigned)__cvta_generic_to_shared(p);
}

#define LDSM_X4(r, addr) \
    asm volatile("ldmatrix.sync.aligned.m8n8.x4.shared.b16 {%0,%1,%2,%3},[%4];" \
        : "=r"((r)[0]), "=r"((r)[1]), "=r"((r)[2]), "=r"((r)[3]) : "r"(addr))

#define LDSM_X4_T(r, addr) \
    asm volatile("ldmatrix.sync.aligned.m8n8.x4.trans.shared.b16 {%0,%1,%2,%3},[%4];" \
        : "=r"((r)[0]), "=r"((r)[1]), "=r"((r)[2]), "=r"((r)[3]) : "r"(addr))

#define MMAF16(C, A, b0, b1) \
    asm volatile("mma.sync.aligned.m16n8k16.row.col.f32.f16.f16.f32 " \
        "{%0,%1,%2,%3},{%4,%5,%6,%7},{%8,%9},{%0,%1,%2,%3};" \
        : "+f"((C)[0]), "+f"((C)[1]), "+f"((C)[2]), "+f"((C)[3]) \
        : "r"((A)[0]), "r"((A)[1]), "r"((A)[2]), "r"((A)[3]), "r"(b0), "r"(b1))

#define CP_ASYNC16(dst, src) \
    asm volatile("cp.async.cg.shared.global [%0],[%1],16;" :: "r"(dst), "l"(src))
#define CP_COMMIT() asm volatile("cp.async.commit_group;")
#define CP_WAIT0()  asm volatile("cp.async.wait_group 0;" ::: "memory")

__global__ __launch_bounds__(256) void attn_mma_kernel(const float* __restrict__ x,
                                                       float* __restrict__ out)
{
    extern __shared__ char smraw[];
    __half* Ahi = (__half*)smraw;              // [128 c][LDA k]
    __half* Alo = Ahi + 128 * LDA;
    __half* B0  = Alo + 128 * LDA;             // [128 k][LDB n], double buffered
    __half* B1  = B0 + 128 * LDB;
    float*  Xs  = (float*)(B1 + 128 * LDB);    // staging [128 k][128 n] fp32

    int b    = blockIdx.y;
    int tid  = threadIdx.x;
    int warp = tid >> 5, lane = tid & 31;

    const float* xb = x + (size_t)b * 128 * 65536;
    float*       ob = out + (size_t)b * 128 * 65536;

    // ---- prefetch tile 0 via cp.async (each thread owns a fixed Xs region)
    {
        int n0 = blockIdx.x * NT * 128;
#pragma unroll
        for (int i = 0; i < 16; ++i) {
            int idx = i * 256 + tid;
            int k = idx >> 5, c4 = idx & 31;
            CP_ASYNC16(smem_u32(Xs + k * 128 + c4 * 4),
                       xb + (size_t)k * 65536 + n0 + c4 * 4);
        }
        CP_COMMIT();
    }

    // ---- A prep: g_St[b] ([c][k] fp32) -> fp16 hi/lo
    {
        const float* Sp = g_St + (size_t)b * 16384;
#pragma unroll
        for (int i = 0; i < 16; ++i) {
            int idx = i * 256 + tid;
            int c = idx >> 5, k4 = (idx & 31) * 4;
            float4 v = *(const float4*)(Sp + c * 128 + k4);
            __half hx = __float2half_rn(v.x), hy = __float2half_rn(v.y);
            __half hz = __float2half_rn(v.z), hw = __float2half_rn(v.w);
            __half* ph = Ahi + c * LDA + k4;
            __half* pl = Alo + c * LDA + k4;
            *(__half2*)(ph)     = __halves2half2(hx, hy);
            *(__half2*)(ph + 2) = __halves2half2(hz, hw);
            *(__half2*)(pl) = __halves2half2(
                __float2half_rn(v.x - __half2float(hx)),
                __float2half_rn(v.y - __half2float(hy)));
            *(__half2*)(pl + 2) = __halves2half2(
                __float2half_rn(v.z - __half2float(hz)),
                __float2half_rn(v.w - __half2float(hw)));
        }
    }

    int mw = (warp >> 1) * 32;        // warp c-offset (4 warps over 128)
    int nw = (warp & 1) * 64;         // warp n-offset (2 warps over 128)
    int r  = lane & 15, q = lane >> 4;

    for (int t = 0; t < NT; ++t) {
        __half* Bp = (t & 1) ? B1 : B0;
        int n0 = (blockIdx.x * NT + t) * 128;

        // ---- wait own staged data, convert own region -> B[p]
        CP_WAIT0();
#pragma unroll
        for (int i = 0; i < 16; ++i) {
            int idx = i * 256 + tid;
            int k = idx >> 5, c4 = idx & 31;
            float4 v = *(const float4*)(Xs + k * 128 + c4 * 4);
            __half* ph = Bp + k * LDB + c4 * 4;
            *(__half2*)(ph)     = __floats2half2_rn(v.x, v.y);
            *(__half2*)(ph + 2) = __floats2half2_rn(v.z, v.w);
        }

        // ---- refill own Xs region for tile t+1 (nobody else reads it)
        if (t + 1 < NT) {
            int n0n = n0 + 128;
#pragma unroll
            for (int i = 0; i < 16; ++i) {
                int idx = i * 256 + tid;
                int k = idx >> 5, c4 = idx & 31;
                CP_ASYNC16(smem_u32(Xs + k * 128 + c4 * 4),
                           xb + (size_t)k * 65536 + n0n + c4 * 4);
            }
            CP_COMMIT();
        }

        __syncthreads();   // B[p] fully written (single barrier per tile)

        float acc[2][8][4];
#pragma unroll
        for (int mf = 0; mf < 2; ++mf)
#pragma unroll
            for (int nf = 0; nf < 8; ++nf)
#pragma unroll
                for (int e = 0; e < 4; ++e) acc[mf][nf][e] = 0.f;

#pragma unroll
        for (int ks = 0; ks < 8; ++ks) {
            int k0 = ks * 16;
            unsigned ah[2][4], al[2][4];
#pragma unroll
            for (int mf = 0; mf < 2; ++mf) {
                LDSM_X4(ah[mf], smem_u32(Ahi + (mw + mf * 16 + r) * LDA + k0 + q * 8));
                LDSM_X4(al[mf], smem_u32(Alo + (mw + mf * 16 + r) * LDA + k0 + q * 8));
            }
#pragma unroll
            for (int nc = 0; nc < 4; ++nc) {
                unsigned bf[4];
                LDSM_X4_T(bf, smem_u32(Bp + (k0 + r) * LDB + nw + nc * 16 + q * 8));
#pragma unroll
                for (int mf = 0; mf < 2; ++mf) {
#pragma unroll
                    for (int h = 0; h < 2; ++h) {
                        float* C = acc[mf][nc * 2 + h];
                        MMAF16(C, ah[mf], bf[2 * h], bf[2 * h + 1]);  // hiA * x
                        MMAF16(C, al[mf], bf[2 * h], bf[2 * h + 1]);  // loA * x
                    }
                }
            }
        }

        // epilogue: store acc to gmem (no barrier needed; next convert uses other B buf)
        int rbase = mw + (lane >> 2);
        int cbase = nw + ((lane & 3) << 1);
#pragma unroll
        for (int mf = 0; mf < 2; ++mf) {
#pragma unroll
            for (int nf = 0; nf < 8; ++nf) {
                float* p0 = ob + (size_t)(rbase + mf * 16) * 65536 + n0 + cbase + nf * 8;
                float* p1 = p0 + 8ull * 65536;
                *(float2*)p0 = make_float2(acc[mf][nf][0], acc[mf][nf][1]);
                *(float2*)p1 = make_float2(acc[mf][nf][2], acc[mf][nf][3]);
            }
        }
    }
}

// ---------------- launch ----------------
extern "C" void kernel_launch(void* const* d_in, const int* in_sizes, int n_in,
                              void* d_out, int out_size)
{
    (void)in_sizes; (void)n_in; (void)out_size;
    const float* x    = (const float*)d_in[0];
    const float* c1w  = (const float*)d_in[1];
    const float* g1   = (const float*)d_in[2];
    const float* b1   = (const float*)d_in[3];
    const float* m1   = (const float*)d_in[4];
    const float* v1   = (const float*)d_in[5];
    const float* a1   = (const float*)d_in[6];
    const float* c2w  = (const float*)d_in[7];
    const float* g2   = (const float*)d_in[8];
    const float* b2   = (const float*)d_in[9];
    const float* m2   = (const float*)d_in[10];
    const float* v2   = (const float*)d_in[11];
    const float* a2   = (const float*)d_in[12];
    float* out = (float*)d_out;

    void* tmp;
    cudaGetSymbolAddress(&tmp, g_p1);  float* p1 = (float*)tmp;
    cudaGetSymbolAddress(&tmp, g_p2);  float* p2 = (float*)tmp;

    // smem: A hi/lo 2*128*136*2 + B double 2*128*136*2 + stage 128*128*4 = 204800
    cudaFuncSetAttribute(gram_partial_kernel,
                         cudaFuncAttributeMaxDynamicSharedMemorySize, 65536);
    cudaFuncSetAttribute(attn_mma_kernel,
                         cudaFuncAttributeMaxDynamicSharedMemorySize, 204800);

    dim3 blk(32, 8);
    dwconv_bn_prelu_kernel<<<dim3(4, 16, 1024), blk>>>(x, p1, c1w, g1, b1, m1, v1, a1,
                                                       256, 256, 128, 128);
    dwconv_bn_prelu_kernel<<<dim3(2, 8, 1024), blk>>>(p1, p2, c2w, g2, b2, m2, v2, a2,
                                                      128, 128, 64, 64);
    gram_partial_kernel<<<dim3(32, 8), 256, 65536>>>();
    softmax_kernel<<<dim3(128, 8), 128>>>();
    attn_mma_kernel<<<dim3(128, 8), 256, 204800>>>(x, out);
}